// round 11
// baseline (speedup 1.0000x reference)
#include <cuda_runtime.h>
#include <cuda_bf16.h>
#include <cstdint>

// FlaxHouseholderRoPE: B=2, S=4096, H=32, D=128, R=2, fp32. SINGLE kernel,
// no SMEM, no barrier, no table.
// One warp per (b,s,h), processing q AND k.
//  - BOTH Householder reflections evaluated against the original x via
//      c0 = 2*dot(x,v0)/(|v0|^2+eps)
//      c1 = 2*(dot(x,v1) - c0*dot(v0,v1))/(|v1|^2+eps)
//      x -= c0*v0 + c1*v1
//    (identical to the sequential recurrence), so ONE 7-value butterfly
//    phase (35 SHFL) replaces two 3-value phases (60 SHFL+FADD) and halves
//    the serial shuffle chain.
//  - Trig: two accurate exp2f (matches reference inv_freq rounding),
//    Cody-Waite 2-term reduction, MUFU sin/cos (err ~1e-6 rad; tol 1e-3).

#define SS 4096
#define HH 32
#define NVEC (2 * SS * HH)        // 262144 vectors per tensor

__device__ __forceinline__ float dot4(float4 a, float4 b) {
    return a.x * b.x + a.y * b.y + a.z * b.z + a.w * b.w;
}

__global__ __launch_bounds__(256)
void hh_rope_kernel(const float* __restrict__ q,
                    const float* __restrict__ k,
                    const float* __restrict__ pos,
                    const float* __restrict__ refl,
                    float* __restrict__ out) {
    const int tid  = threadIdx.x;
    const int warp = tid >> 5;
    const int lane = tid & 31;
    const int idx  = blockIdx.x * 8 + warp;          // (b*S+s)*H + h
    const int h    = idx & (HH - 1);
    const int s    = (idx >> 5) & (SS - 1);

    // ---- all loads FIRST (max MLP: 4 independent LDG.128) ----
    const size_t off = (size_t)idx * 32 + lane;
    float4 xq = __ldcs(reinterpret_cast<const float4*>(q) + off);
    float4 xk = __ldcs(reinterpret_cast<const float4*>(k) + off);
    const float4 v0 = __ldg(reinterpret_cast<const float4*>(refl) + (h * 2 + 0) * 32 + lane);
    const float4 v1 = __ldg(reinterpret_cast<const float4*>(refl) + (h * 2 + 1) * 32 + lane);

    // ---- inline trig for this lane's two pairs (overlaps LDG latency) ----
    const float LOG2_BASE = 13.287712379549449f;     // log2(10000)
    const float p  = pos[s];
    const float f0 = exp2f(-(float)(4 * lane)     * (1.0f / 128.0f) * LOG2_BASE);
    const float f1 = exp2f(-(float)(4 * lane + 2) * (1.0f / 128.0f) * LOG2_BASE);
    const float a0 = p * f0;                         // == reference's fp32 angle
    const float a1 = p * f1;
    // Cody-Waite: a <= 4096 -> n <= 652; n*6.28125 exact in fp32
    const float INV2PI = 0.15915494309189535f;
    const float C1 = 6.28125f;
    const float C2 = 1.9353071795864769e-3f;         // 2*pi - C1
    const float n0 = rintf(a0 * INV2PI);
    const float n1 = rintf(a1 * INV2PI);
    float r0 = fmaf(-n0, C1, a0);  r0 = fmaf(-n0, C2, r0);
    float r1 = fmaf(-n1, C1, a1);  r1 = fmaf(-n1, C2, r1);
    const float c0 = __cosf(r0), s0 = __sinf(r0);    // MUFU on reduced range
    const float c1 = __cosf(r1), s1 = __sinf(r1);

    // ---- single-phase 7-value butterfly for both reflections ----
    float dq0 = dot4(xq, v0), dq1 = dot4(xq, v1);
    float dk0 = dot4(xk, v0), dk1 = dot4(xk, v1);
    float sq0 = dot4(v0, v0), sq1 = dot4(v1, v1);
    float g01 = dot4(v0, v1);
    #pragma unroll
    for (int o = 16; o; o >>= 1) {
        dq0 += __shfl_xor_sync(0xffffffffu, dq0, o);
        dq1 += __shfl_xor_sync(0xffffffffu, dq1, o);
        dk0 += __shfl_xor_sync(0xffffffffu, dk0, o);
        dk1 += __shfl_xor_sync(0xffffffffu, dk1, o);
        sq0 += __shfl_xor_sync(0xffffffffu, sq0, o);
        sq1 += __shfl_xor_sync(0xffffffffu, sq1, o);
        g01 += __shfl_xor_sync(0xffffffffu, g01, o);
    }
    const float inv0 = __frcp_rn(sq0 + 1e-6f);
    const float inv1 = __frcp_rn(sq1 + 1e-6f);
    const float cq0 = 2.0f * dq0 * inv0;
    const float ck0 = 2.0f * dk0 * inv0;
    const float cq1 = 2.0f * (dq1 - cq0 * g01) * inv1;
    const float ck1 = 2.0f * (dk1 - ck0 * g01) * inv1;

    xq.x -= cq0 * v0.x + cq1 * v1.x;  xq.y -= cq0 * v0.y + cq1 * v1.y;
    xq.z -= cq0 * v0.z + cq1 * v1.z;  xq.w -= cq0 * v0.w + cq1 * v1.w;
    xk.x -= ck0 * v0.x + ck1 * v1.x;  xk.y -= ck0 * v0.y + ck1 * v1.y;
    xk.z -= ck0 * v0.z + ck1 * v1.z;  xk.w -= ck0 * v0.w + ck1 * v1.w;

    // ---- RoPE with in-register cos/sin ----
    float4 oq, ok;
    oq.x = xq.x * c0 - xq.y * s0;
    oq.y = xq.x * s0 + xq.y * c0;
    oq.z = xq.z * c1 - xq.w * s1;
    oq.w = xq.z * s1 + xq.w * c1;
    ok.x = xk.x * c0 - xk.y * s0;
    ok.y = xk.x * s0 + xk.y * c0;
    ok.z = xk.z * c1 - xk.w * s1;
    ok.w = xk.z * s1 + xk.w * c1;

    float4* out4 = reinterpret_cast<float4*>(out);
    __stcs(out4 + off, oq);                              // q half
    __stcs(out4 + (size_t)NVEC * 32 + off, ok);          // k half
}

extern "C" void kernel_launch(void* const* d_in, const int* in_sizes, int n_in,
                              void* d_out, int out_size) {
    const float* q    = (const float*)d_in[0];
    const float* k    = (const float*)d_in[1];
    const float* pos  = (const float*)d_in[2];
    const float* refl = (const float*)d_in[3];
    float* out = (float*)d_out;

    // one warp per (b,s,h): 262144 warps, 8 per block -> 32768 blocks
    hh_rope_kernel<<<NVEC / 8, 256>>>(q, k, pos, refl, out);
}

// round 12
// speedup vs baseline: 1.0773x; 1.0773x over previous
#include <cuda_runtime.h>
#include <cuda_bf16.h>
#include <cstdint>

// FlaxHouseholderRoPE: B=2, S=4096, H=32, D=128, R=2, fp32. Two launches.
// R4's proven main kernel (77.4us, DRAM 79%) + a cheap prologue:
//   - g_tab built with Cody-Waite reduction + MUFU sin/cos (~30 instrs/entry
//     vs libdevice sincosf's ~150; accuracy proven in rounds 7-8).
//   - g_u = v * sqrt(2/(|v|^2+eps)) so each reflection is x -= dot(x,u)*u
//     (== the reference recurrence 2*dot(x,v)/(|v|^2+eps) * v).

#define SS 4096
#define HH 32
#define NVEC (2 * SS * HH)        // 262144 vectors per tensor
#define TAB_BLOCKS 512

__device__ float4 g_tab[SS * 32];      // (cos,sin,cos,sin) per (s,lane)
__device__ float4 g_u[HH * 2 * 32];    // normalized reflectors

__device__ __forceinline__ float dot4(float4 a, float4 b) {
    return a.x * b.x + a.y * b.y + a.z * b.z + a.w * b.w;
}

// accurate-enough sincos for a <= 4096: 2-term Cody-Waite + MUFU
__device__ __forceinline__ float2 fast_sincos(float a) {
    const float INV2PI = 0.15915494309189535f;
    const float C1 = 6.28125f;                    // n*C1 exact for n <= 652
    const float C2 = 1.9353071795864769e-3f;      // 2*pi - C1
    const float n = rintf(a * INV2PI);
    float r = fmaf(-n, C1, a);
    r = fmaf(-n, C2, r);
    return make_float2(__cosf(r), __sinf(r));
}

__global__ __launch_bounds__(256)
void prologue_kernel(const float* __restrict__ pos,
                     const float* __restrict__ refl) {
    if (blockIdx.x < TAB_BLOCKS) {
        const int j = blockIdx.x * 256 + threadIdx.x;   // 0 .. 131071
        const int s = j >> 5;
        const int t = j & 31;
        const float p = pos[s];
        const float LOG2_BASE = 13.287712379549449f;    // log2(10000)
        const float f0 = exp2f(-(float)(4 * t)     * (1.0f / 128.0f) * LOG2_BASE);
        const float f1 = exp2f(-(float)(4 * t + 2) * (1.0f / 128.0f) * LOG2_BASE);
        const float2 cs0 = fast_sincos(p * f0);
        const float2 cs1 = fast_sincos(p * f1);
        g_tab[j] = make_float4(cs0.x, cs0.y, cs1.x, cs1.y);
    } else {
        // one warp per reflector row (h,r): 64 rows over 8 blocks
        const int row  = (blockIdx.x - TAB_BLOCKS) * 8 + ((int)threadIdx.x >> 5);
        const int lane = threadIdx.x & 31;
        if (row < HH * 2) {
            const float4 v = reinterpret_cast<const float4*>(refl)[row * 32 + lane];
            float sq = dot4(v, v);
            #pragma unroll
            for (int o = 16; o; o >>= 1) sq += __shfl_xor_sync(0xffffffffu, sq, o);
            const float sc = sqrtf(2.0f / (sq + 1e-6f));
            g_u[row * 32 + lane] = make_float4(v.x * sc, v.y * sc, v.z * sc, v.w * sc);
        }
    }
}

// ===== main kernel: byte-identical logic to round 4's proven 77.4us loop =====
__global__ __launch_bounds__(256)
void hh_rope_kernel(const float* __restrict__ q,
                    const float* __restrict__ k,
                    float* __restrict__ out) {
    const int idx  = (blockIdx.x * blockDim.x + threadIdx.x) >> 5;  // (b*S+s)*H + h
    const int lane = threadIdx.x & 31;

    const int h = idx & (HH - 1);
    const int s = (idx >> 5) & (SS - 1);

    const size_t off = (size_t)idx * 32 + lane;

    // streamed loads (coalesced LDG.128, evict-first)
    float4 xq = __ldcs(reinterpret_cast<const float4*>(q) + off);
    float4 xk = __ldcs(reinterpret_cast<const float4*>(k) + off);

    // two sequential normalized-Householder reflections on q and k
    #pragma unroll
    for (int r = 0; r < 2; ++r) {
        const float4 u = g_u[(h * 2 + r) * 32 + lane];   // L1 hit
        float dq = dot4(xq, u);
        float dk = dot4(xk, u);
        #pragma unroll
        for (int o = 16; o; o >>= 1) {
            dq += __shfl_xor_sync(0xffffffffu, dq, o);
            dk += __shfl_xor_sync(0xffffffffu, dk, o);
        }
        xq.x -= dq * u.x;  xq.y -= dq * u.y;  xq.z -= dq * u.z;  xq.w -= dq * u.w;
        xk.x -= dk * u.x;  xk.y -= dk * u.y;  xk.z -= dk * u.z;  xk.w -= dk * u.w;
    }

    // RoPE via table (same row across the block's 8 warps -> L1 broadcast)
    const float4 cs = g_tab[s * 32 + lane];   // (c0, s0, c1, s1)

    float4 oq, ok;
    oq.x = xq.x * cs.x - xq.y * cs.y;
    oq.y = xq.x * cs.y + xq.y * cs.x;
    oq.z = xq.z * cs.z - xq.w * cs.w;
    oq.w = xq.z * cs.w + xq.w * cs.z;
    ok.x = xk.x * cs.x - xk.y * cs.y;
    ok.y = xk.x * cs.y + xk.y * cs.x;
    ok.z = xk.z * cs.z - xk.w * cs.w;
    ok.w = xk.z * cs.w + xk.w * cs.z;

    float4* out4 = reinterpret_cast<float4*>(out);
    __stcs(out4 + off, oq);                              // q half
    __stcs(out4 + (size_t)NVEC * 32 + off, ok);          // k half
}

extern "C" void kernel_launch(void* const* d_in, const int* in_sizes, int n_in,
                              void* d_out, int out_size) {
    const float* q    = (const float*)d_in[0];
    const float* k    = (const float*)d_in[1];
    const float* pos  = (const float*)d_in[2];
    const float* refl = (const float*)d_in[3];
    float* out = (float*)d_out;

    prologue_kernel<<<TAB_BLOCKS + 8, 256>>>(pos, refl);
    // one warp per (b,s,h): 262144 warps, 8 per block
    hh_rope_kernel<<<NVEC / 8, 256>>>(q, k, out);
}

// round 13
// speedup vs baseline: 1.0994x; 1.0206x over previous
#include <cuda_runtime.h>
#include <cuda_bf16.h>
#include <cstdint>

// FlaxHouseholderRoPE: B=2, S=4096, H=32, D=128, R=2, fp32. SINGLE kernel,
// no SMEM, no barrier, no prologue.
// One warp per (b,s,h), processing q AND k.
//  - inv_freq values 10000^(-i/64) are input-independent constants: baked in
//    as a compile-time double-precision table (256 B, __device__, L1-resident).
//    One LDG.64 replaces two runtime exp2f chains (~30 instrs/thread).
//  - Cody-Waite 2-term reduction + MUFU sin/cos (err ~1e-6 rad; tol 1e-3).
//  - Householder: fused 3-value butterfly, coef = 2*dot/(|v|^2+eps) — the
//    exact reference recurrence.

#define SS 4096
#define HH 32
#define NVEC (2 * SS * HH)        // 262144 vectors per tensor

// 10000^(-1/64), correctly rounded double
constexpr double R64 = 0.8659643233600653;
constexpr double rpow(int i) {
    double v = 1.0;
    for (int j = 0; j < i; ++j) v *= R64;
    return v;
}
#define FQ(l) { (float)rpow(2*(l)), (float)rpow(2*(l)+1) }
__device__ const float2 g_freq[32] = {
    FQ(0),  FQ(1),  FQ(2),  FQ(3),  FQ(4),  FQ(5),  FQ(6),  FQ(7),
    FQ(8),  FQ(9),  FQ(10), FQ(11), FQ(12), FQ(13), FQ(14), FQ(15),
    FQ(16), FQ(17), FQ(18), FQ(19), FQ(20), FQ(21), FQ(22), FQ(23),
    FQ(24), FQ(25), FQ(26), FQ(27), FQ(28), FQ(29), FQ(30), FQ(31)
};

__device__ __forceinline__ float dot4(float4 a, float4 b) {
    return a.x * b.x + a.y * b.y + a.z * b.z + a.w * b.w;
}

__global__ __launch_bounds__(256)
void hh_rope_kernel(const float* __restrict__ q,
                    const float* __restrict__ k,
                    const float* __restrict__ pos,
                    const float* __restrict__ refl,
                    float* __restrict__ out) {
    const int tid  = threadIdx.x;
    const int warp = tid >> 5;
    const int lane = tid & 31;
    const int idx  = blockIdx.x * 8 + warp;          // (b*S+s)*H + h
    const int h    = idx & (HH - 1);
    const int s    = (idx >> 5) & (SS - 1);

    // ---- streamed loads FIRST (coalesced LDG.128) ----
    const size_t off = (size_t)idx * 32 + lane;
    float4 xq = __ldcs(reinterpret_cast<const float4*>(q) + off);
    float4 xk = __ldcs(reinterpret_cast<const float4*>(k) + off);

    // ---- trig for this lane's two pairs (freqs from baked table) ----
    const float2 f  = g_freq[lane];                  // LDG.64, L1 hit
    const float  p  = pos[s];
    const float  a0 = p * f.x;                       // == reference's fp32 angle
    const float  a1 = p * f.y;
    // Cody-Waite: a <= 4096 -> n <= 652; n*6.28125 exact in fp32
    const float INV2PI = 0.15915494309189535f;
    const float C1 = 6.28125f;
    const float C2 = 1.9353071795864769e-3f;         // 2*pi - C1
    const float n0 = rintf(a0 * INV2PI);
    const float n1 = rintf(a1 * INV2PI);
    float r0 = fmaf(-n0, C1, a0);  r0 = fmaf(-n0, C2, r0);
    float r1 = fmaf(-n1, C1, a1);  r1 = fmaf(-n1, C2, r1);
    const float c0 = __cosf(r0), s0 = __sinf(r0);    // MUFU on reduced range
    const float c1 = __cosf(r1), s1 = __sinf(r1);

    // ---- two sequential Householder reflections, fused 3-value butterfly ----
    #pragma unroll
    for (int r = 0; r < 2; ++r) {
        const float4 v = __ldg(reinterpret_cast<const float4*>(refl)
                               + (h * 2 + r) * 32 + lane);   // L1 hit after wave 1
        float dq = dot4(xq, v);
        float dk = dot4(xk, v);
        float sq = dot4(v, v);
        #pragma unroll
        for (int o = 16; o; o >>= 1) {
            dq += __shfl_xor_sync(0xffffffffu, dq, o);
            dk += __shfl_xor_sync(0xffffffffu, dk, o);
            sq += __shfl_xor_sync(0xffffffffu, sq, o);
        }
        const float inv = __frcp_rn(sq + 1e-6f);
        const float cq = 2.0f * dq * inv;
        const float ck = 2.0f * dk * inv;
        xq.x -= cq * v.x;  xq.y -= cq * v.y;  xq.z -= cq * v.z;  xq.w -= cq * v.w;
        xk.x -= ck * v.x;  xk.y -= ck * v.y;  xk.z -= ck * v.z;  xk.w -= ck * v.w;
    }

    // ---- RoPE with in-register cos/sin ----
    float4 oq, ok;
    oq.x = xq.x * c0 - xq.y * s0;
    oq.y = xq.x * s0 + xq.y * c0;
    oq.z = xq.z * c1 - xq.w * s1;
    oq.w = xq.z * s1 + xq.w * c1;
    ok.x = xk.x * c0 - xk.y * s0;
    ok.y = xk.x * s0 + xk.y * c0;
    ok.z = xk.z * c1 - xk.w * s1;
    ok.w = xk.z * s1 + xk.w * c1;

    float4* out4 = reinterpret_cast<float4*>(out);
    __stcs(out4 + off, oq);                              // q half
    __stcs(out4 + (size_t)NVEC * 32 + off, ok);          // k half
}

extern "C" void kernel_launch(void* const* d_in, const int* in_sizes, int n_in,
                              void* d_out, int out_size) {
    const float* q    = (const float*)d_in[0];
    const float* k    = (const float*)d_in[1];
    const float* pos  = (const float*)d_in[2];
    const float* refl = (const float*)d_in[3];
    float* out = (float*)d_out;

    // one warp per (b,s,h): 262144 warps, 8 per block -> 32768 blocks
    hh_rope_kernel<<<NVEC / 8, 256>>>(q, k, pos, refl, out);
}